// round 2
// baseline (speedup 1.0000x reference)
#include <cuda_runtime.h>
#include <cstdint>

#define M_TOTAL 16384
#define K_DIM   2048
#define E_DIM   64
#define TOPK    8

#define BM   64
#define BK   32
#define ASTR 76            // a_sm row stride (floats): 2*BK=64 data + 12 pad
                           // -> STS.128 aligned (76*4%16==0), m vs m+4 banks differ (4*76%32==16)

// One-time W transpose scratch: Wt[k][e]
__device__ float Wt_g[(size_t)K_DIM * E_DIM];

__global__ void transpose_w(const float* __restrict__ W, float* __restrict__ Wt) {
    int t = blockIdx.x * blockDim.x + threadIdx.x;     // 131072 total
    int e = t & (E_DIM - 1);
    int k = t >> 6;
    Wt[(size_t)k * E_DIM + e] = W[(size_t)e * K_DIM + k];
}

// Packed fp32x2 FMA (two independent lane FMAs, each .rn — per-lane rounding
// identical to scalar fmaf).
__device__ __forceinline__ float2 ffma2(float2 a, float2 b, float2 c) {
    float2 d;
    asm("fma.rn.f32x2 %0, %1, %2, %3;"
        : "=l"(reinterpret_cast<unsigned long long&>(d))
        : "l"(reinterpret_cast<unsigned long long&>(a)),
          "l"(reinterpret_cast<unsigned long long&>(b)),
          "l"(reinterpret_cast<unsigned long long&>(c)));
    return d;
}

// logits[m][e] = sequential-k FMA chain: acc = fma(X[m][k], W[e][k], acc), k ascending.
// f32x2 lanes pack two experts (e, e+1) for one m — per-lane accumulation order
// is a pure sequential scalar FMA chain, matching cublas-SGEMM / Eigen-gebp rounding.
__global__ __launch_bounds__(256, 2)
void router_gemm(const float* __restrict__ X, const float* __restrict__ Wt,
                 float* __restrict__ logits) {
    __shared__ float a_sm[BM][ASTR];       // duplicated: a_sm[m][2k]=a_sm[m][2k+1]=X[m][k]
    __shared__ float b_sm[BK][E_DIM];      // b_sm[k][e]

    const int tid = threadIdx.x;
    const int mg  = tid >> 4;    // 0..15
    const int eg  = tid & 15;    // 0..15
    const int m0  = blockIdx.x * BM;

    float2 acc[4][2];
    #pragma unroll
    for (int i = 0; i < 4; i++) { acc[i][0] = make_float2(0.f, 0.f); acc[i][1] = make_float2(0.f, 0.f); }

    for (int k0 = 0; k0 < K_DIM; k0 += BK) {
        // A tile: 64m x 32k floats = 512 float4; 2 per thread; store duplicated.
        #pragma unroll
        for (int i = 0; i < 2; i++) {
            int f   = tid + i * 256;         // 0..511
            int row = f >> 3;                // 0..63
            int q   = f & 7;                 // float4 index within row
            float4 v = *reinterpret_cast<const float4*>(
                &X[(size_t)(m0 + row) * K_DIM + k0 + q * 4]);
            float4 d0 = make_float4(v.x, v.x, v.y, v.y);
            float4 d1 = make_float4(v.z, v.z, v.w, v.w);
            *reinterpret_cast<float4*>(&a_sm[row][q * 8])     = d0;
            *reinterpret_cast<float4*>(&a_sm[row][q * 8 + 4]) = d1;
        }
        // B tile: Wt rows k0..k0+31 are a contiguous 2048-float block.
        {
            const float4* src = reinterpret_cast<const float4*>(&Wt[(size_t)k0 * E_DIM]);
            float4* dst = reinterpret_cast<float4*>(&b_sm[0][0]);
            dst[tid]       = src[tid];
            dst[tid + 256] = src[tid + 256];
        }
        __syncthreads();

        #pragma unroll 16
        for (int kk = 0; kk < BK; kk++) {
            float4 b4 = *reinterpret_cast<const float4*>(&b_sm[kk][eg * 4]);
            float2 bp0 = make_float2(b4.x, b4.y);
            float2 bp1 = make_float2(b4.z, b4.w);
            #pragma unroll
            for (int i = 0; i < 4; i++) {
                float2 ap = *reinterpret_cast<const float2*>(&a_sm[mg * 4 + i][kk * 2]);
                acc[i][0] = ffma2(ap, bp0, acc[i][0]);
                acc[i][1] = ffma2(ap, bp1, acc[i][1]);
            }
        }
        __syncthreads();
    }

    #pragma unroll
    for (int i = 0; i < 4; i++) {
        int m = m0 + mg * 4 + i;
        float4 o = make_float4(acc[i][0].x, acc[i][0].y, acc[i][1].x, acc[i][1].y);
        *reinterpret_cast<float4*>(&logits[(size_t)m * E_DIM + eg * 4]) = o;
    }
}

// Per-token top-8 (strict > keeps earlier index on ties, matching jax top_k)
// + fp32 softmax over selected logits.
__global__ void topk_softmax(const float* __restrict__ logits,
                             float* __restrict__ wout,
                             float* __restrict__ eout) {
    int t = blockIdx.x * blockDim.x + threadIdx.x;
    if (t >= M_TOTAL) return;

    const float4* row = reinterpret_cast<const float4*>(logits + (size_t)t * E_DIM);

    float tv[TOPK];
    int   ti[TOPK];
    #pragma unroll
    for (int i = 0; i < TOPK; i++) { tv[i] = -3.4e38f; ti[i] = 0; }

    #pragma unroll
    for (int q = 0; q < E_DIM / 4; q++) {
        float4 v4 = row[q];
        float vs[4] = {v4.x, v4.y, v4.z, v4.w};
        #pragma unroll
        for (int u = 0; u < 4; u++) {
            float v = vs[u];
            int   e = q * 4 + u;
            if (v > tv[TOPK - 1]) {
                tv[TOPK - 1] = v; ti[TOPK - 1] = e;
                #pragma unroll
                for (int j = TOPK - 1; j > 0; j--) {
                    if (tv[j] > tv[j - 1]) {
                        float tf = tv[j]; tv[j] = tv[j - 1]; tv[j - 1] = tf;
                        int   tx = ti[j]; ti[j] = ti[j - 1]; ti[j - 1] = tx;
                    }
                }
            }
        }
    }

    float m = tv[0];
    float ev[TOPK];
    float s = 0.f;
    #pragma unroll
    for (int i = 0; i < TOPK; i++) { ev[i] = __expf(tv[i] - m); s += ev[i]; }
    float inv = 1.f / s;
    #pragma unroll
    for (int i = 0; i < TOPK; i++) {
        wout[(size_t)t * TOPK + i] = ev[i] * inv;
        eout[(size_t)t * TOPK + i] = (float)ti[i];
    }
}

extern "C" void kernel_launch(void* const* d_in, const int* in_sizes, int n_in,
                              void* d_out, int out_size) {
    const float* X = (const float*)d_in[0];   // [4,4096,2048] fp32
    const float* W = (const float*)d_in[1];   // [64,2048]     fp32

    float* out    = (float*)d_out;
    float* logits = out;                                   // 16384*64
    float* wts    = out + (size_t)M_TOTAL * E_DIM;         // 16384*8
    float* exps   = wts + (size_t)M_TOTAL * TOPK;          // 16384*8 (indices as float)

    float* Wt;
    cudaGetSymbolAddress((void**)&Wt, Wt_g);

    transpose_w<<<(K_DIM * E_DIM) / 256, 256>>>(W, Wt);
    router_gemm<<<M_TOTAL / BM, 256>>>(X, Wt, logits);
    topk_softmax<<<(M_TOTAL + 255) / 256, 256>>>(logits, wts, exps);
}

// round 3
// speedup vs baseline: 1.4954x; 1.4954x over previous
#include <cuda_runtime.h>
#include <cstdint>

#define M_TOTAL 16384
#define K_DIM   2048
#define E_DIM   64
#define TOPK    8

#define BM    128
#define BK    32
#define ASTR  68            // a_sm row stride in floats: 64 dup'd data + 4 pad (17 chunks -> odd)
#define NTILE (K_DIM / BK)  // 64

// One-time W transpose scratch: Wt[k][e]
__device__ float Wt_g[(size_t)K_DIM * E_DIM];

// Coalesced reads (consecutive t -> consecutive k of one expert row); scattered
// 4B writes are absorbed by L2/write sectors. ~1 MB traffic.
__global__ void transpose_w(const float* __restrict__ W, float* __restrict__ Wt) {
    int t = blockIdx.x * blockDim.x + threadIdx.x;   // 131072
    int e = t >> 11;            // 0..63
    int k = t & (K_DIM - 1);    // 0..2047
    Wt[(size_t)k * E_DIM + e] = W[(size_t)e * K_DIM + k];
}

// Packed fp32x2 FMA; per-lane rounding identical to scalar fmaf.
__device__ __forceinline__ float2 ffma2(float2 a, float2 b, float2 c) {
    float2 d;
    asm("fma.rn.f32x2 %0, %1, %2, %3;"
        : "=l"(reinterpret_cast<unsigned long long&>(d))
        : "l"(reinterpret_cast<unsigned long long&>(a)),
          "l"(reinterpret_cast<unsigned long long&>(b)),
          "l"(reinterpret_cast<unsigned long long&>(c)));
    return d;
}

// Fused: logits GEMM (sequential-k FMA chain per (m,e), ascending k — same
// rounding as the round-2 passing kernel) + per-token top-8 + softmax.
// Thread tile: 4 m-rows x 8 experts (eg*4+0..3 and eg*4+32..35), f32x2 packs
// expert pairs. a duplicated in smem so (a,a) pairs load as one LDS.128 per 2kk.
__global__ __launch_bounds__(256, 1)
void router_fused(const float* __restrict__ X, const float* __restrict__ Wt,
                  float* __restrict__ logits,
                  float* __restrict__ wout, float* __restrict__ eout) {
    __shared__ float smem[BM * ASTR + BK * E_DIM];   // 10752 floats = 42 KB
    float* a_sm = smem;                // [BM][ASTR], dup'd: [m][2k]=[m][2k+1]=X[m][k]
    float* b_sm = smem + BM * ASTR;    // [BK][E_DIM]

    const int tid = threadIdx.x;
    const int eg  = tid & 7;     // 8 expert groups
    const int mg  = tid >> 3;    // 32 m groups x 4 rows
    const int m0  = blockIdx.x * BM;

    float2 acc[4][4];
    #pragma unroll
    for (int i = 0; i < 4; i++)
        #pragma unroll
        for (int j = 0; j < 4; j++) acc[i][j] = make_float2(0.f, 0.f);

    // ---- prefetch registers for next tile ----
    float4 pa[4];   // a: rows f>>3, quad f&7
    float4 pb[2];   // b: contiguous Wt block

    // rows/quads for this thread's a-loads
    int arow[4], aq[4];
    #pragma unroll
    for (int i = 0; i < 4; i++) { int f = tid + i * 256; arow[i] = f >> 3; aq[i] = f & 7; }

    // preload tile 0
    #pragma unroll
    for (int i = 0; i < 4; i++)
        pa[i] = *reinterpret_cast<const float4*>(&X[(size_t)(m0 + arow[i]) * K_DIM + aq[i] * 4]);
    {
        const float4* src = reinterpret_cast<const float4*>(Wt);
        pb[0] = src[tid];
        pb[1] = src[tid + 256];
    }

    for (int t = 0; t < NTILE; t++) {
        // ---- store prefetched tile to smem ----
        #pragma unroll
        for (int i = 0; i < 4; i++) {
            float4 v = pa[i];
            *reinterpret_cast<float4*>(&a_sm[arow[i] * ASTR + aq[i] * 8]) =
                make_float4(v.x, v.x, v.y, v.y);
            *reinterpret_cast<float4*>(&a_sm[arow[i] * ASTR + aq[i] * 8 + 4]) =
                make_float4(v.z, v.z, v.w, v.w);
        }
        {
            float4* dst = reinterpret_cast<float4*>(b_sm);
            dst[tid]       = pb[0];
            dst[tid + 256] = pb[1];
        }
        __syncthreads();

        // ---- prefetch next tile ----
        if (t + 1 < NTILE) {
            int kn = (t + 1) * BK;
            #pragma unroll
            for (int i = 0; i < 4; i++)
                pa[i] = *reinterpret_cast<const float4*>(
                    &X[(size_t)(m0 + arow[i]) * K_DIM + kn + aq[i] * 4]);
            const float4* src = reinterpret_cast<const float4*>(&Wt[(size_t)kn * E_DIM]);
            pb[0] = src[tid];
            pb[1] = src[tid + 256];
        }

        // ---- mainloop over this tile ----
        #pragma unroll
        for (int kk = 0; kk < BK; kk += 2) {
            float4 a4[4];
            #pragma unroll
            for (int i = 0; i < 4; i++)
                a4[i] = *reinterpret_cast<const float4*>(&a_sm[(mg * 4 + i) * ASTR + kk * 2]);

            #pragma unroll
            for (int s = 0; s < 2; s++) {
                float4 b0 = *reinterpret_cast<const float4*>(&b_sm[(kk + s) * E_DIM + eg * 4]);
                float4 b1 = *reinterpret_cast<const float4*>(&b_sm[(kk + s) * E_DIM + eg * 4 + 32]);
                float2 bp0 = make_float2(b0.x, b0.y);
                float2 bp1 = make_float2(b0.z, b0.w);
                float2 bp2 = make_float2(b1.x, b1.y);
                float2 bp3 = make_float2(b1.z, b1.w);
                #pragma unroll
                for (int i = 0; i < 4; i++) {
                    float2 ap = s ? make_float2(a4[i].z, a4[i].w)
                                  : make_float2(a4[i].x, a4[i].y);
                    acc[i][0] = ffma2(ap, bp0, acc[i][0]);
                    acc[i][1] = ffma2(ap, bp1, acc[i][1]);
                    acc[i][2] = ffma2(ap, bp2, acc[i][2]);
                    acc[i][3] = ffma2(ap, bp3, acc[i][3]);
                }
            }
        }
        __syncthreads();
    }

    // ---- epilogue: write logits (global) + stage in smem for topk ----
    #pragma unroll
    for (int i = 0; i < 4; i++) {
        int m = mg * 4 + i;
        float4 lo = make_float4(acc[i][0].x, acc[i][0].y, acc[i][1].x, acc[i][1].y);
        float4 hi = make_float4(acc[i][2].x, acc[i][2].y, acc[i][3].x, acc[i][3].y);
        *reinterpret_cast<float4*>(&logits[(size_t)(m0 + m) * E_DIM + eg * 4])      = lo;
        *reinterpret_cast<float4*>(&logits[(size_t)(m0 + m) * E_DIM + eg * 4 + 32]) = hi;
        *reinterpret_cast<float4*>(&smem[m * ASTR + eg * 4])      = lo;
        *reinterpret_cast<float4*>(&smem[m * ASTR + eg * 4 + 32]) = hi;
    }
    __syncthreads();

    // ---- top-8 + softmax: one thread per token (threads 0..127) ----
    if (tid < BM) {
        const float* row = &smem[tid * ASTR];
        float tv[TOPK];
        int   ti[TOPK];
        #pragma unroll
        for (int i = 0; i < TOPK; i++) { tv[i] = -3.4e38f; ti[i] = 0; }

        #pragma unroll
        for (int q = 0; q < E_DIM / 4; q++) {
            float4 v4 = *reinterpret_cast<const float4*>(&row[q * 4]);
            float vs[4] = {v4.x, v4.y, v4.z, v4.w};
            #pragma unroll
            for (int u = 0; u < 4; u++) {
                float v = vs[u];
                int   e = q * 4 + u;
                if (v > tv[TOPK - 1]) {
                    tv[TOPK - 1] = v; ti[TOPK - 1] = e;
                    #pragma unroll
                    for (int j = TOPK - 1; j > 0; j--) {
                        if (tv[j] > tv[j - 1]) {   // strict: ties keep earlier index
                            float tf = tv[j]; tv[j] = tv[j - 1]; tv[j - 1] = tf;
                            int   tx = ti[j]; ti[j] = ti[j - 1]; ti[j - 1] = tx;
                        }
                    }
                }
            }
        }

        float mx = tv[0];
        float ev[TOPK], ssum = 0.f;
        #pragma unroll
        for (int i = 0; i < TOPK; i++) { ev[i] = __expf(tv[i] - mx); ssum += ev[i]; }
        float inv = 1.f / ssum;
        size_t tok = (size_t)(m0 + tid);
        #pragma unroll
        for (int i = 0; i < TOPK; i++) {
            wout[tok * TOPK + i] = ev[i] * inv;
            eout[tok * TOPK + i] = (float)ti[i];
        }
    }
}

extern "C" void kernel_launch(void* const* d_in, const int* in_sizes, int n_in,
                              void* d_out, int out_size) {
    const float* X = (const float*)d_in[0];   // [4,4096,2048] fp32
    const float* W = (const float*)d_in[1];   // [64,2048]     fp32

    float* out    = (float*)d_out;
    float* logits = out;                                   // 16384*64
    float* wts    = out + (size_t)M_TOTAL * E_DIM;         // 16384*8
    float* exps   = wts + (size_t)M_TOTAL * TOPK;          // 16384*8 (indices as float)

    float* Wt;
    cudaGetSymbolAddress((void**)&Wt, Wt_g);

    transpose_w<<<(K_DIM * E_DIM) / 256, 256>>>(W, Wt);
    router_fused<<<M_TOTAL / BM, 256>>>(X, Wt, logits, wts, exps);
}